// round 1
// baseline (speedup 1.0000x reference)
#include <cuda_runtime.h>
#include <math.h>

#define B_ 128
#define N_ 512
#define H_ 512
#define M_ (B_*N_)   // 65536

// ---------------- scratch (static device allocations) ----------------
__device__ float g_gx[B_*3*H_];
__device__ float g_gh[B_*3*H_];
__device__ float g_off_enc[B_*H_];
__device__ float g_off_tgt[B_*H_];
__device__ float g_off_state[B_*H_];
__device__ float g_offP[B_*H_];
__device__ float g_offPt[B_*H_];
__device__ float g_scores[2*B_*N_];      // enc rows 0..127, tgt rows 128..255
__device__ float g_ctx[B_*H_];
__device__ float g_ctxt[B_*H_];
__device__ float g_Sptr[(size_t)M_*H_];  // 134 MB: static_hidden @ ptrW_static^T

// ---------------- small NT GEMM: warp per output element ----------------
// C[m*N + n] = (Cinit? Cinit[m*N+n] : 0) + sum_k A[m*lda+k] * W[n*ldw+k], K = 512
__global__ void small_gemm(const float* __restrict__ A, int lda,
                           const float* __restrict__ W, int ldw,
                           const float* __restrict__ Cinit,
                           float* __restrict__ C, int N)
{
    int m = blockIdx.y;
    int n = blockIdx.x * 8 + (threadIdx.x >> 5);
    int lane = threadIdx.x & 31;
    if (n >= N) return;
    const float* a = A + (size_t)m * lda;
    const float* w = W + (size_t)n * ldw;
    float sum = 0.f;
#pragma unroll
    for (int c = 0; c < 4; c++) {
        int k = c * 128 + lane * 4;
        float4 av = *(const float4*)(a + k);
        float4 wv = *(const float4*)(w + k);
        sum += av.x*wv.x + av.y*wv.y + av.z*wv.z + av.w*wv.w;
    }
#pragma unroll
    for (int o = 16; o; o >>= 1) sum += __shfl_xor_sync(0xffffffffu, sum, o);
    if (lane == 0) {
        float base = Cinit ? Cinit[(size_t)m * N + n] : 0.f;
        C[(size_t)m * N + n] = base + sum;
    }
}

// ---------------- GRU gates ----------------
__global__ void gru_gate(const float* __restrict__ bih, const float* __restrict__ bhh,
                         const float* __restrict__ hprev, float* __restrict__ hnew)
{
    int b = blockIdx.x, h = threadIdx.x;
    const float* gx = g_gx + b * 1536;
    const float* gh = g_gh + b * 1536;
    float r = 1.f / (1.f + expf(-(gx[h]        + bih[h]        + gh[h]        + bhh[h])));
    float z = 1.f / (1.f + expf(-(gx[512+h]    + bih[512+h]    + gh[512+h]    + bhh[512+h])));
    float n = tanhf(gx[1024+h] + bih[1024+h] + r * (gh[1024+h] + bhh[1024+h]));
    float hp = hprev[b*512 + h];
    hnew[b*512 + h] = (1.f - z) * n + z * hp;
}

// ---------------- big GEMM: 128x128x16 tile, 8x8 microtile ----------------
// MODE 0: out[m*512 + h] = static[m,:] . W[h,:]                      (store)
// MODE 1: out[m] = sum_h v[h] * tanh(static[m,:] . W[h,:] + off[b,h]) (score)
template<int MODE>
__global__ void __launch_bounds__(256, 2)
big_kernel(const float* __restrict__ A,
           const float* __restrict__ W, int ldw,
           const float* __restrict__ off,
           const float* __restrict__ v,
           float* __restrict__ out)
{
    __shared__ float As[16][128];
    __shared__ float Bs[16][128];
    __shared__ float red[(MODE == 1) ? 128 * 17 : 1];

    const int tid = threadIdx.x;
    const int tx = tid & 15;
    const int ty = tid >> 4;
    const int m0 = blockIdx.x * 128;
    const int b  = m0 >> 9;           // 128 rows always within one batch (128 | 512)

    float s[8];
#pragma unroll
    for (int i = 0; i < 8; i++) s[i] = 0.f;

    const int mm = tid & 127;
    const int kq = tid >> 7;          // 0 or 1; second load covers kq+2
    const float* Aptr = A + (size_t)(m0 + mm) * 512 + kq * 4;

    for (int ct = 0; ct < 4; ct++) {
        const int n0 = ct * 128;
        float acc[8][8];
#pragma unroll
        for (int i = 0; i < 8; i++)
#pragma unroll
            for (int j = 0; j < 8; j++) acc[i][j] = 0.f;

        const float* Wptr = W + (size_t)(n0 + mm) * ldw + kq * 4;

        for (int k0 = 0; k0 < 512; k0 += 16) {
#pragma unroll
            for (int it = 0; it < 2; it++) {
                int kqq = kq + it * 2;     // 0..3
                float4 av = *(const float4*)(Aptr + k0 + it * 8);
                float4 bv = *(const float4*)(Wptr + k0 + it * 8);
                As[kqq*4+0][mm] = av.x; As[kqq*4+1][mm] = av.y;
                As[kqq*4+2][mm] = av.z; As[kqq*4+3][mm] = av.w;
                Bs[kqq*4+0][mm] = bv.x; Bs[kqq*4+1][mm] = bv.y;
                Bs[kqq*4+2][mm] = bv.z; Bs[kqq*4+3][mm] = bv.w;
            }
            __syncthreads();
#pragma unroll
            for (int k = 0; k < 16; k++) {
                float4 a0 = *(const float4*)&As[k][ty*4];
                float4 a1 = *(const float4*)&As[k][64 + ty*4];
                float4 b0 = *(const float4*)&Bs[k][tx*4];
                float4 b1 = *(const float4*)&Bs[k][64 + tx*4];
                float ar[8] = {a0.x,a0.y,a0.z,a0.w,a1.x,a1.y,a1.z,a1.w};
                float br[8] = {b0.x,b0.y,b0.z,b0.w,b1.x,b1.y,b1.z,b1.w};
#pragma unroll
                for (int i = 0; i < 8; i++)
#pragma unroll
                    for (int j = 0; j < 8; j++)
                        acc[i][j] = fmaf(ar[i], br[j], acc[i][j]);
            }
            __syncthreads();
        }

        if (MODE == 0) {
#pragma unroll
            for (int i = 0; i < 8; i++) {
                int row = (i < 4) ? (ty*4 + i) : (64 + ty*4 + i - 4);
                float* o = out + (size_t)(m0 + row) * 512 + n0;
                *(float4*)(o + tx*4)      = make_float4(acc[i][0],acc[i][1],acc[i][2],acc[i][3]);
                *(float4*)(o + 64 + tx*4) = make_float4(acc[i][4],acc[i][5],acc[i][6],acc[i][7]);
            }
        } else {
            float offv[8], vv[8];
#pragma unroll
            for (int j = 0; j < 8; j++) {
                int col = n0 + ((j < 4) ? (tx*4 + j) : (64 + tx*4 + j - 4));
                offv[j] = off[b * 512 + col];
                vv[j]   = v[col];
            }
#pragma unroll
            for (int i = 0; i < 8; i++)
#pragma unroll
                for (int j = 0; j < 8; j++)
                    s[i] += vv[j] * tanhf(acc[i][j] + offv[j]);
        }
    }

    if (MODE == 1) {
#pragma unroll
        for (int i = 0; i < 8; i++) {
            int row = (i < 4) ? (ty*4 + i) : (64 + ty*4 + i - 4);
            red[row * 17 + tx] = s[i];
        }
        __syncthreads();
        if (tid < 128) {
            float t = 0.f;
#pragma unroll
            for (int j = 0; j < 16; j++) t += red[tid * 17 + j];
            out[m0 + tid] = t;
        }
    }
}

// ---------------- softmax over N=512 (in place), one row per block ----------------
__global__ void softmax512(float* __restrict__ data)
{
    int row = blockIdx.x;
    float* p = data + (size_t)row * 512;
    int tid = threadIdx.x; // 256
    float v0 = p[tid], v1 = p[tid + 256];
    __shared__ float sm[8];
    float mx = fmaxf(v0, v1);
#pragma unroll
    for (int o = 16; o; o >>= 1) mx = fmaxf(mx, __shfl_xor_sync(0xffffffffu, mx, o));
    if ((tid & 31) == 0) sm[tid >> 5] = mx;
    __syncthreads();
    float m = sm[0];
#pragma unroll
    for (int i = 1; i < 8; i++) m = fmaxf(m, sm[i]);
    float e0 = expf(v0 - m), e1 = expf(v1 - m);
    __syncthreads();
    float ss = e0 + e1;
#pragma unroll
    for (int o = 16; o; o >>= 1) ss += __shfl_xor_sync(0xffffffffu, ss, o);
    if ((tid & 31) == 0) sm[tid >> 5] = ss;
    __syncthreads();
    float tot = sm[0]+sm[1]+sm[2]+sm[3]+sm[4]+sm[5]+sm[6]+sm[7];
    float inv = 1.f / tot;
    p[tid] = e0 * inv;
    p[tid + 256] = e1 * inv;
}

// ---------------- both contexts in one pass over static_hidden ----------------
__global__ void context_kernel(const float* __restrict__ sh,
                               const float* __restrict__ attn, // [2*B][512]
                               float* __restrict__ ctx, float* __restrict__ ctxt)
{
    int b = blockIdx.x;
    int h = threadIdx.x; // 512
    __shared__ float ae[512], at[512];
    ae[h] = attn[b*512 + h];
    at[h] = attn[65536 + b*512 + h];
    __syncthreads();
    const float* sp = sh + (size_t)b * 512 * 512 + h;
    float ce = 0.f, ctv = 0.f;
#pragma unroll 4
    for (int n = 0; n < 512; n++) {
        float sv = sp[(size_t)n * 512];
        ce  = fmaf(ae[n], sv, ce);
        ctv = fmaf(at[n], sv, ctv);
    }
    ctx[b*512 + h] = ce;
    ctxt[b*512 + h] = ctv;
}

// ---------------- final pointer probs: 5*tanh(S+offP) + tanh(S+offPt), dot v ----------------
__global__ void probs_kernel(const float* __restrict__ S,
                             const float* __restrict__ offP,
                             const float* __restrict__ offPt,
                             const float* __restrict__ v,
                             float* __restrict__ out)
{
    int m = blockIdx.x;
    int b = m >> 9;
    int tid = threadIdx.x; // 128
    const float* srow = S + (size_t)m * 512;
    float sum = 0.f;
#pragma unroll
    for (int c = 0; c < 4; c++) {
        int h = tid + c * 128;
        float sv = srow[h];
        sum += v[h] * (5.f * tanhf(sv + offP[b*512 + h]) + tanhf(sv + offPt[b*512 + h]));
    }
#pragma unroll
    for (int o = 16; o; o >>= 1) sum += __shfl_xor_sync(0xffffffffu, sum, o);
    __shared__ float ws[4];
    if ((tid & 31) == 0) ws[tid >> 5] = sum;
    __syncthreads();
    if (tid == 0) out[m] = ws[0] + ws[1] + ws[2] + ws[3];
}

// ---------------- host ----------------
static float* sym_addr(const void* s)
{
    void* p = nullptr;
    cudaGetSymbolAddress(&p, s);
    return (float*)p;
}

extern "C" void kernel_launch(void* const* d_in, const int* in_sizes, int n_in,
                              void* d_out, int out_size)
{
    const float* static_h  = (const float*)d_in[0];
    const float* state_emb = (const float*)d_in[1];
    const float* dec_h     = (const float*)d_in[2];
    const float* tgt_h     = (const float*)d_in[3];
    const float* last_hh   = (const float*)d_in[4];
    const float* ptr_v     = (const float*)d_in[5];
    const float* ptr_W     = (const float*)d_in[6];
    const float* enc_v     = (const float*)d_in[7];
    const float* enc_W     = (const float*)d_in[8];
    const float* tgt_v     = (const float*)d_in[9];
    const float* tgt_W     = (const float*)d_in[10];
    const float* w_ih      = (const float*)d_in[11];
    const float* w_hh      = (const float*)d_in[12];
    const float* b_ih      = (const float*)d_in[13];
    const float* b_hh      = (const float*)d_in[14];

    float* out  = (float*)d_out;        // probs: [0, 65536)
    float* hnew = out + 65536;          // new_last_hh: [65536, 131072)

    float* p_gx       = sym_addr(g_gx);
    float* p_gh       = sym_addr(g_gh);
    float* p_off_enc  = sym_addr(g_off_enc);
    float* p_off_tgt  = sym_addr(g_off_tgt);
    float* p_off_st   = sym_addr(g_off_state);
    float* p_offP     = sym_addr(g_offP);
    float* p_offPt    = sym_addr(g_offPt);
    float* p_scores   = sym_addr(g_scores);
    float* p_ctx      = sym_addr(g_ctx);
    float* p_ctxt     = sym_addr(g_ctxt);
    float* p_Sptr     = sym_addr(g_Sptr);

    dim3 g192(192, 128), g64(64, 128);

    // GRU pre-activations and gates
    small_gemm<<<g192, 256>>>(dec_h,   512, w_ih, 512, nullptr, p_gx, 1536);
    small_gemm<<<g192, 256>>>(last_hh, 512, w_hh, 512, nullptr, p_gh, 1536);
    gru_gate<<<128, 512>>>(b_ih, b_hh, last_hh, hnew);

    // per-batch offsets (dynamic halves of the concat GEMMs)
    small_gemm<<<g64, 256>>>(hnew,      512, enc_W + 512,  1024, nullptr, p_off_enc, 512);
    small_gemm<<<g64, 256>>>(tgt_h,     512, tgt_W + 512,  1024, nullptr, p_off_tgt, 512);
    small_gemm<<<g64, 256>>>(state_emb, 512, ptr_W + 1024, 1536, nullptr, p_off_st,  512);

    // big static GEMMs: fused attention scores + pointer-static store
    big_kernel<1><<<512, 256>>>(static_h, enc_W, 1024, p_off_enc, enc_v, p_scores);
    big_kernel<1><<<512, 256>>>(static_h, tgt_W, 1024, p_off_tgt, tgt_v, p_scores + 65536);
    big_kernel<0><<<512, 256>>>(static_h, ptr_W, 1536, nullptr,   nullptr, p_Sptr);

    // softmax both attentions, then both contexts in one static pass
    softmax512<<<256, 256>>>(p_scores);
    context_kernel<<<128, 512>>>(static_h, p_scores, p_ctx, p_ctxt);

    // pointer offsets (context part + state part)
    small_gemm<<<g64, 256>>>(p_ctx,  512, ptr_W + 512, 1536, p_off_st, p_offP,  512);
    small_gemm<<<g64, 256>>>(p_ctxt, 512, ptr_W + 512, 1536, p_off_st, p_offPt, 512);

    // final fused probs
    probs_kernel<<<65536, 128>>>(p_Sptr, p_offP, p_offPt, ptr_v, out);
}

// round 3
// speedup vs baseline: 2.8202x; 2.8202x over previous
#include <cuda_runtime.h>
#include <math.h>
#include <cstdint>

#define B_ 128
#define N_ 512
#define H_ 512
#define M_ (B_*N_)   // 65536

// ---------------- scratch (static device allocations) ----------------
__device__ float g_gx[B_*3*H_];
__device__ float g_gh[B_*3*H_];
__device__ float g_off_enc[B_*H_];
__device__ float g_off_tgt[B_*H_];
__device__ float g_off_state[B_*H_];
__device__ float g_offP[B_*H_];
__device__ float g_offPt[B_*H_];
__device__ float g_scores[2*B_*N_];      // enc rows 0..127, tgt rows 128..255
__device__ float g_ctx[B_*H_];
__device__ float g_ctxt[B_*H_];
__device__ float g_Ar[(size_t)M_*H_];    // 128 MB: tf32-rounded static_hidden
__device__ float g_Wenc[H_*H_];          // tf32-rounded static halves (ld = 512)
__device__ float g_Wtgt[H_*H_];
__device__ float g_Wptr[H_*H_];

// ---------------- helpers ----------------
__device__ __forceinline__ uint32_t smem_u32(const void* p) {
    uint32_t a;
    asm("{ .reg .u64 t; cvta.to.shared.u64 t, %1; cvt.u32.u64 %0, t; }" : "=r"(a) : "l"(p));
    return a;
}
__device__ __forceinline__ void cp16(uint32_t dst, const float* src) {
    asm volatile("cp.async.cg.shared.global [%0], [%1], 16;" :: "r"(dst), "l"(src));
}
__device__ __forceinline__ uint32_t rna_tf32(float f) {
    uint32_t u;
    asm("cvt.rna.tf32.f32 %0, %1;" : "=r"(u) : "f"(f));
    return u;
}
__device__ __forceinline__ float fast_tanh(float x) {
    float r;
    asm("tanh.approx.f32 %0, %1;" : "=f"(r) : "f"(x));
    return r;
}
#define MMA_TF32(c, a, b) \
    asm volatile("mma.sync.aligned.m16n8k8.row.col.f32.tf32.tf32.f32 " \
        "{%0,%1,%2,%3}, {%4,%5,%6,%7}, {%8,%9}, {%0,%1,%2,%3};" \
        : "+f"((c)[0]), "+f"((c)[1]), "+f"((c)[2]), "+f"((c)[3]) \
        : "r"((a)[0]), "r"((a)[1]), "r"((a)[2]), "r"((a)[3]), \
          "r"((b)[0]), "r"((b)[1]))

// ---------------- tf32 pre-round kernels ----------------
__global__ void round_a_kernel(const float* __restrict__ in, float* __restrict__ out)
{
    int i = blockIdx.x * blockDim.x + threadIdx.x;   // over float4s
    float4 f = ((const float4*)in)[i];
    uint4 u;
    u.x = rna_tf32(f.x); u.y = rna_tf32(f.y); u.z = rna_tf32(f.z); u.w = rna_tf32(f.w);
    ((uint4*)out)[i] = u;
}
__global__ void round_w_kernel(const float* __restrict__ W, int ldw, float* __restrict__ out)
{
    int n = blockIdx.x, t = threadIdx.x;  // 128 threads, row of 512
    float4 f = *(const float4*)(W + (size_t)n * ldw + t * 4);
    uint4 u;
    u.x = rna_tf32(f.x); u.y = rna_tf32(f.y); u.z = rna_tf32(f.z); u.w = rna_tf32(f.w);
    *(uint4*)(out + n * 512 + t * 4) = u;
}

// ================= tensor-core GEMM (mma.sync tf32) + fused tanh-dot =================
// Per CTA: rows [m0, m0+128) x all 512 cols of  A @ W^T  (K=512), two column passes of 256.
// DUAL=0: out[m] = sum_h v[h] * tanh(acc + off1[b,h])
// DUAL=1: out[m] = sum_h v[h] * (5*tanh(acc + off1[b,h]) + tanh(acc + off2[b,h]))
// smem float map: [0,512) v | [512,1024) off1 | [1024,1536) off2 | [1536,2048) red
//                 [2048,12288) A bufs 4 x 128 x 20 | [12288,32768) B bufs 4 x 256 x 20
template<bool DUAL>
__global__ void __launch_bounds__(256, 1)
tc_mma(const float* __restrict__ A,       // tf32-rounded, ld=512
       const float* __restrict__ W,       // tf32-rounded, ld=512
       const float* __restrict__ off1,
       const float* __restrict__ off2,
       const float* __restrict__ v,
       float* __restrict__ out)
{
    extern __shared__ float smf[];
    const uint32_t sbase = smem_u32(smf);
    const int tid = threadIdx.x;
    const int wid = tid >> 5, lane = tid & 31;
    const int wm = wid & 1, wn = wid >> 1;       // warp tile 64(M) x 64(N); CTA 128 x 256
    const int lq = lane & 3, lg = lane >> 2;
    const int m0 = blockIdx.x << 7;
    const int b  = m0 >> 9;

    constexpr int SV = 0, SO1 = 512, SO2 = 1024, RED = 1536;
    constexpr int ABO = 2048, BBO = 12288;
    constexpr int NC = 64;                        // 2 col-passes x 32 k-chunks
    constexpr int PF = 3;

    float* sv  = smf + SV;
    float* so1 = smf + SO1;
    float* so2 = smf + SO2;
    for (int i = tid; i < 512; i += 256) {
        sv[i]  = v[i];
        so1[i] = off1[b * 512 + i];
        if (DUAL) so2[i] = off2[b * 512 + i];
    }

    // ---- pipeline issue helper (chunk c: k = (c&31)*16, n-pass = c>>5) ----
    auto issue = [&](int c) {
        if (c < NC) {
            const int buf = c & 3;
            const int kc  = (c & 31) << 4;
            const int n0s = (c >> 5) << 8;
            const uint32_t ab = sbase + (ABO + buf * 2560) * 4;
            const uint32_t bb = sbase + (BBO + buf * 5120) * 4;
#pragma unroll
            for (int t = 0; t < 2; t++) {
                int o = tid + 256 * t, m = o >> 2, q = o & 3;
                cp16(ab + (m * 20 + q * 4) * 4, A + (size_t)(m0 + m) * 512 + kc + q * 4);
            }
#pragma unroll
            for (int j = 0; j < 4; j++) {
                int o = tid + 256 * j, n = o >> 2, q = o & 3;
                cp16(bb + (n * 20 + q * 4) * 4, W + (size_t)(n0s + n) * 512 + kc + q * 4);
            }
        }
        asm volatile("cp.async.commit_group;");
    };

    float acc[4][8][4];
#pragma unroll
    for (int mb = 0; mb < 4; mb++)
#pragma unroll
        for (int nb = 0; nb < 8; nb++)
#pragma unroll
            for (int r = 0; r < 4; r++) acc[mb][nb][r] = 0.f;
    float s[8];
#pragma unroll
    for (int i = 0; i < 8; i++) s[i] = 0.f;

    issue(0); issue(1); issue(2);

    for (int c = 0; c < NC; c++) {
        asm volatile("cp.async.wait_group 2;");
        __syncthreads();          // chunk c landed everywhere; all done computing c-1
        issue(c + PF);

        const int buf = c & 3;
        const float* As = smf + ABO + buf * 2560;
        const float* Bs = smf + BBO + buf * 5120;
#pragma unroll
        for (int st = 0; st < 2; st++) {
            const int k0 = st * 8 + lq;
            uint32_t afr[4][4], bfr[8][2];
#pragma unroll
            for (int mb = 0; mb < 4; mb++) {
                int r = wm * 64 + mb * 16 + lg;
                afr[mb][0] = __float_as_uint(As[r * 20 + k0]);
                afr[mb][1] = __float_as_uint(As[(r + 8) * 20 + k0]);
                afr[mb][2] = __float_as_uint(As[r * 20 + k0 + 4]);
                afr[mb][3] = __float_as_uint(As[(r + 8) * 20 + k0 + 4]);
            }
#pragma unroll
            for (int nb = 0; nb < 8; nb++) {
                int n = wn * 64 + nb * 8 + lg;
                bfr[nb][0] = __float_as_uint(Bs[n * 20 + k0]);
                bfr[nb][1] = __float_as_uint(Bs[n * 20 + k0 + 4]);
            }
#pragma unroll
            for (int mb = 0; mb < 4; mb++)
#pragma unroll
                for (int nb = 0; nb < 8; nb++)
                    MMA_TF32(acc[mb][nb], afr[mb], bfr[nb]);
        }

        // ---- per-column-pass fused epilogue ----
        if ((c & 31) == 31) {
            const int n0 = (c >> 5) << 8;
#pragma unroll
            for (int mb = 0; mb < 4; mb++)
#pragma unroll
                for (int nb = 0; nb < 8; nb++) {
                    int col = n0 + wn * 64 + nb * 8 + lq * 2;
#pragma unroll
                    for (int r = 0; r < 4; r++) {
                        int cc = col + (r & 1);
                        float av = acc[mb][nb][r];
                        float t1 = fast_tanh(av + so1[cc]);
                        float val;
                        if (DUAL) {
                            float t2 = fast_tanh(av + so2[cc]);
                            val = sv[cc] * (5.f * t1 + t2);
                        } else {
                            val = sv[cc] * t1;
                        }
                        s[mb * 2 + (r >> 1)] += val;
                        acc[mb][nb][r] = 0.f;
                    }
                }
        }
    }

    // ---- final reduction: quad shuffle, cross-warp smem ----
#pragma unroll
    for (int i = 0; i < 8; i++) {
        s[i] += __shfl_xor_sync(0xffffffffu, s[i], 1);
        s[i] += __shfl_xor_sync(0xffffffffu, s[i], 2);
    }
    float* red = smf + RED;
    if (lq == 0) {
#pragma unroll
        for (int i = 0; i < 8; i++) {
            int row = wm * 64 + (i >> 1) * 16 + (i & 1) * 8 + lg;
            red[row * 4 + wn] = s[i];
        }
    }
    __syncthreads();
    if (tid < 128) {
        float* rr = red + tid * 4;
        out[m0 + tid] = rr[0] + rr[1] + rr[2] + rr[3];
    }
}

// ---------------- small NT GEMM: warp per output element ----------------
__global__ void small_gemm(const float* __restrict__ A, int lda,
                           const float* __restrict__ W, int ldw,
                           const float* __restrict__ Cinit,
                           float* __restrict__ C, int N)
{
    int m = blockIdx.y;
    int n = blockIdx.x * 8 + (threadIdx.x >> 5);
    int lane = threadIdx.x & 31;
    if (n >= N) return;
    const float* a = A + (size_t)m * lda;
    const float* w = W + (size_t)n * ldw;
    float sum = 0.f;
#pragma unroll
    for (int c = 0; c < 4; c++) {
        int k = c * 128 + lane * 4;
        float4 av = *(const float4*)(a + k);
        float4 wv = *(const float4*)(w + k);
        sum += av.x*wv.x + av.y*wv.y + av.z*wv.z + av.w*wv.w;
    }
#pragma unroll
    for (int o = 16; o; o >>= 1) sum += __shfl_xor_sync(0xffffffffu, sum, o);
    if (lane == 0) {
        float base = Cinit ? Cinit[(size_t)m * N + n] : 0.f;
        C[(size_t)m * N + n] = base + sum;
    }
}

// ---------------- GRU gates ----------------
__global__ void gru_gate(const float* __restrict__ bih, const float* __restrict__ bhh,
                         const float* __restrict__ hprev, float* __restrict__ hnew)
{
    int b = blockIdx.x, h = threadIdx.x;
    const float* gx = g_gx + b * 1536;
    const float* gh = g_gh + b * 1536;
    float r = 1.f / (1.f + expf(-(gx[h]     + bih[h]     + gh[h]     + bhh[h])));
    float z = 1.f / (1.f + expf(-(gx[512+h] + bih[512+h] + gh[512+h] + bhh[512+h])));
    float n = tanhf(gx[1024+h] + bih[1024+h] + r * (gh[1024+h] + bhh[1024+h]));
    float hp = hprev[b*512 + h];
    hnew[b*512 + h] = (1.f - z) * n + z * hp;
}

// ---------------- softmax over N=512 (in place), one row per block ----------------
__global__ void softmax512(float* __restrict__ data)
{
    int row = blockIdx.x;
    float* p = data + (size_t)row * 512;
    int tid = threadIdx.x; // 256
    float v0 = p[tid], v1 = p[tid + 256];
    __shared__ float sm[8];
    float mx = fmaxf(v0, v1);
#pragma unroll
    for (int o = 16; o; o >>= 1) mx = fmaxf(mx, __shfl_xor_sync(0xffffffffu, mx, o));
    if ((tid & 31) == 0) sm[tid >> 5] = mx;
    __syncthreads();
    float m = sm[0];
#pragma unroll
    for (int i = 1; i < 8; i++) m = fmaxf(m, sm[i]);
    float e0 = expf(v0 - m), e1 = expf(v1 - m);
    __syncthreads();
    float ss = e0 + e1;
#pragma unroll
    for (int o = 16; o; o >>= 1) ss += __shfl_xor_sync(0xffffffffu, ss, o);
    if ((tid & 31) == 0) sm[tid >> 5] = ss;
    __syncthreads();
    float tot = sm[0]+sm[1]+sm[2]+sm[3]+sm[4]+sm[5]+sm[6]+sm[7];
    float inv = 1.f / tot;
    p[tid] = e0 * inv;
    p[tid + 256] = e1 * inv;
}

// ---------------- both contexts in one pass over static_hidden ----------------
__global__ void context_kernel(const float* __restrict__ sh,
                               const float* __restrict__ attn, // [2*B][512]
                               float* __restrict__ ctx, float* __restrict__ ctxt)
{
    int b = blockIdx.x;
    int h = threadIdx.x; // 512
    __shared__ float ae[512], at[512];
    ae[h] = attn[b*512 + h];
    at[h] = attn[65536 + b*512 + h];
    __syncthreads();
    const float* sp = sh + (size_t)b * 512 * 512 + h;
    float ce = 0.f, ctv = 0.f;
#pragma unroll 4
    for (int n = 0; n < 512; n++) {
        float sv2 = sp[(size_t)n * 512];
        ce  = fmaf(ae[n], sv2, ce);
        ctv = fmaf(at[n], sv2, ctv);
    }
    ctx[b*512 + h] = ce;
    ctxt[b*512 + h] = ctv;
}

// ---------------- host ----------------
static float* sym_addr(const void* s)
{
    void* p = nullptr;
    cudaGetSymbolAddress(&p, s);
    return (float*)p;
}

extern "C" void kernel_launch(void* const* d_in, const int* in_sizes, int n_in,
                              void* d_out, int out_size)
{
    const float* static_h  = (const float*)d_in[0];
    const float* state_emb = (const float*)d_in[1];
    const float* dec_h     = (const float*)d_in[2];
    const float* tgt_h     = (const float*)d_in[3];
    const float* last_hh   = (const float*)d_in[4];
    const float* ptr_v     = (const float*)d_in[5];
    const float* ptr_W     = (const float*)d_in[6];
    const float* enc_v     = (const float*)d_in[7];
    const float* enc_W     = (const float*)d_in[8];
    const float* tgt_v     = (const float*)d_in[9];
    const float* tgt_W     = (const float*)d_in[10];
    const float* w_ih      = (const float*)d_in[11];
    const float* w_hh      = (const float*)d_in[12];
    const float* b_ih      = (const float*)d_in[13];
    const float* b_hh      = (const float*)d_in[14];

    float* out  = (float*)d_out;        // probs: [0, 65536)
    float* hnew = out + 65536;          // new_last_hh: [65536, 131072)

    float* p_gx      = sym_addr(g_gx);
    float* p_gh      = sym_addr(g_gh);
    float* p_off_enc = sym_addr(g_off_enc);
    float* p_off_tgt = sym_addr(g_off_tgt);
    float* p_off_st  = sym_addr(g_off_state);
    float* p_offP    = sym_addr(g_offP);
    float* p_offPt   = sym_addr(g_offPt);
    float* p_scores  = sym_addr(g_scores);
    float* p_ctx     = sym_addr(g_ctx);
    float* p_ctxt    = sym_addr(g_ctxt);
    float* p_Ar      = sym_addr(g_Ar);
    float* p_Wenc    = sym_addr(g_Wenc);
    float* p_Wtgt    = sym_addr(g_Wtgt);
    float* p_Wptr    = sym_addr(g_Wptr);

    constexpr int SMEM_BYTES = 32768 * 4;   // 128 KB
    cudaFuncSetAttribute(tc_mma<false>, cudaFuncAttributeMaxDynamicSharedMemorySize, SMEM_BYTES);
    cudaFuncSetAttribute(tc_mma<true>,  cudaFuncAttributeMaxDynamicSharedMemorySize, SMEM_BYTES);

    dim3 g192(192, 128), g64(64, 128);

    // tf32 pre-rounding (rna — keeps the GEMM error unbiased)
    round_a_kernel<<<32768, 256>>>(static_h, p_Ar);
    round_w_kernel<<<512, 128>>>(enc_W, 1024, p_Wenc);
    round_w_kernel<<<512, 128>>>(tgt_W, 1024, p_Wtgt);
    round_w_kernel<<<512, 128>>>(ptr_W, 1536, p_Wptr);

    // GRU pre-activations + independent offsets (exact fp32)
    small_gemm<<<g192, 256>>>(dec_h,   512, w_ih, 512, nullptr, p_gx, 1536);
    small_gemm<<<g192, 256>>>(last_hh, 512, w_hh, 512, nullptr, p_gh, 1536);
    small_gemm<<<g64, 256>>>(tgt_h,     512, tgt_W + 512,  1024, nullptr, p_off_tgt, 512);
    small_gemm<<<g64, 256>>>(state_emb, 512, ptr_W + 1024, 1536, nullptr, p_off_st,  512);
    gru_gate<<<128, 512>>>(b_ih, b_hh, last_hh, hnew);
    small_gemm<<<g64, 256>>>(hnew,      512, enc_W + 512,  1024, nullptr, p_off_enc, 512);

    // big tensor-core GEMMs: fused attention scores
    tc_mma<false><<<512, 256, SMEM_BYTES>>>(p_Ar, p_Wenc, p_off_enc, nullptr, enc_v, p_scores);
    tc_mma<false><<<512, 256, SMEM_BYTES>>>(p_Ar, p_Wtgt, p_off_tgt, nullptr, tgt_v, p_scores + 65536);

    // softmax both attentions, then both contexts in one static pass
    softmax512<<<256, 256>>>(p_scores);
    context_kernel<<<128, 512>>>(static_h, p_scores, p_ctx, p_ctxt);

    // pointer offsets (context part + state part)
    small_gemm<<<g64, 256>>>(p_ctx,  512, ptr_W + 512, 1536, p_off_st, p_offP,  512);
    small_gemm<<<g64, 256>>>(p_ctxt, 512, ptr_W + 512, 1536, p_off_st, p_offPt, 512);

    // final fused pointer GEMM: 5*tanh(S+offP) + tanh(S+offPt), dot ptr_v
    tc_mma<true><<<512, 256, SMEM_BYTES>>>(p_Ar, p_Wptr, p_offP, p_offPt, ptr_v, out);
}

// round 5
// speedup vs baseline: 4.4332x; 1.5719x over previous
#include <cuda_runtime.h>
#include <cuda_fp16.h>
#include <math.h>
#include <cstdint>

#define B_ 128
#define N_ 512
#define H_ 512
#define M_ (B_*N_)   // 65536

// ---------------- scratch (static device allocations) ----------------
__device__ float g_gx[B_*3*H_];
__device__ float g_gh[B_*3*H_];
__device__ float g_off_enc[B_*H_];
__device__ float g_off_tgt[B_*H_];
__device__ float g_off_state[B_*H_];
__device__ float g_offP[B_*H_];
__device__ float g_offPt[B_*H_];
__device__ float g_scores[2*B_*N_];      // enc rows 0..127, tgt rows 128..255
__device__ float g_ctx[B_*H_];
__device__ float g_ctxt[B_*H_];
__device__ __half g_Ah[(size_t)M_*H_];   // 64 MB: fp16 static_hidden
__device__ __half g_Wenc[H_*H_];         // fp16 static halves (ld = 512)
__device__ __half g_Wtgt[H_*H_];
__device__ __half g_Wptr[H_*H_];

// ---------------- helpers ----------------
__device__ __forceinline__ uint32_t smem_u32(const void* p) {
    uint32_t a;
    asm("{ .reg .u64 t; cvta.to.shared.u64 t, %1; cvt.u32.u64 %0, t; }" : "=r"(a) : "l"(p));
    return a;
}
__device__ __forceinline__ void cp16(uint32_t dst, const void* src) {
    asm volatile("cp.async.cg.shared.global [%0], [%1], 16;" :: "r"(dst), "l"(src));
}
__device__ __forceinline__ float fast_tanh(float x) {
    float r;
    asm("tanh.approx.f32 %0, %1;" : "=f"(r) : "f"(x));
    return r;
}
__device__ __forceinline__ uint32_t h2u(__half2 h) {
    uint32_t u;
    memcpy(&u, &h, 4);
    return u;
}
#define MMA_F16(c, a, b) \
    asm volatile("mma.sync.aligned.m16n8k16.row.col.f32.f16.f16.f32 " \
        "{%0,%1,%2,%3}, {%4,%5,%6,%7}, {%8,%9}, {%0,%1,%2,%3};" \
        : "+f"((c)[0]), "+f"((c)[1]), "+f"((c)[2]), "+f"((c)[3]) \
        : "r"((a)[0]), "r"((a)[1]), "r"((a)[2]), "r"((a)[3]), \
          "r"((b)[0]), "r"((b)[1]))

// ---------------- fp32 -> fp16 conversion kernels ----------------
__global__ void f2h_a(const float* __restrict__ in, __half* __restrict__ out)
{
    size_t i = (size_t)blockIdx.x * blockDim.x + threadIdx.x;  // 8 floats per thread
    const float4* in4 = (const float4*)in;
    float4 f0 = in4[2*i], f1 = in4[2*i + 1];
    uint4 u = make_uint4(h2u(__floats2half2_rn(f0.x, f0.y)),
                         h2u(__floats2half2_rn(f0.z, f0.w)),
                         h2u(__floats2half2_rn(f1.x, f1.y)),
                         h2u(__floats2half2_rn(f1.z, f1.w)));
    ((uint4*)out)[i] = u;
}
__global__ void f2h_w(const float* __restrict__ W, int ldw, __half* __restrict__ out)
{
    int n = blockIdx.x, t = threadIdx.x;  // 64 threads x 8 floats
    const float4* row = (const float4*)(W + (size_t)n * ldw);
    float4 f0 = row[2*t], f1 = row[2*t + 1];
    uint4 u = make_uint4(h2u(__floats2half2_rn(f0.x, f0.y)),
                         h2u(__floats2half2_rn(f0.z, f0.w)),
                         h2u(__floats2half2_rn(f1.x, f1.y)),
                         h2u(__floats2half2_rn(f1.z, f1.w)));
    ((uint4*)(out + (size_t)n * 512))[t] = u;
}

// ================= tensor-core GEMM (mma.sync f16, f32 accum) + fused tanh-dot ==========
// Per CTA: rows [m0, m0+128) x all 512 cols of A @ W^T (K=512), two column passes of 256.
// DUAL=0: out[m] = sum_h v[h] * tanh(acc + off1[b,h])
// DUAL=1: out[m] = sum_h v[h] * (5*tanh(acc + off1[b,h]) + tanh(acc + off2[b,h]))
// smem u32 map: [0,512) v | [512,1024) off1 | [1024,1536) off2 | [1536,2048) red
//               [2048,9728) A bufs 3 x 128 x 20 | [9728,25088) B bufs 3 x 256 x 20
template<bool DUAL>
__global__ void __launch_bounds__(256, 1)
tc_mma(const __half* __restrict__ A,     // ld = 512
       const __half* __restrict__ W,     // ld = 512
       const float* __restrict__ off1,
       const float* __restrict__ off2,
       const float* __restrict__ v,
       float* __restrict__ out)
{
    extern __shared__ uint32_t smu[];
    const uint32_t sbase = smem_u32(smu);
    const int tid = threadIdx.x;
    const int wid = tid >> 5, lane = tid & 31;
    const int wm = wid & 1, wn = wid >> 1;       // warp tile 64(M) x 64(N); CTA 128 x 256
    const int lq = lane & 3, lg = lane >> 2;
    const int m0 = blockIdx.x << 7;
    const int b  = m0 >> 9;

    constexpr int SV = 0, SO1 = 512, SO2 = 1024, RED = 1536;
    constexpr int ABO = 2048, BBO = 9728;
    constexpr int NC = 32;                        // 2 col-passes x 16 K32-chunks

    float* sv  = (float*)(smu + SV);
    float* so1 = (float*)(smu + SO1);
    float* so2 = (float*)(smu + SO2);
    for (int i = tid; i < 512; i += 256) {
        sv[i]  = v[i];
        so1[i] = off1[b * 512 + i];
        if (DUAL) so2[i] = off2[b * 512 + i];
    }

    // chunk c: k = (c&15)*32, n-pass = c>>4; buffer c%3
    auto issue = [&](int c) {
        if (c < NC) {
            const int buf = c % 3;
            const int kc  = (c & 15) << 5;        // in halves
            const int n0s = (c >> 4) << 8;
            const uint32_t ab = sbase + (ABO + buf * 2560) * 4;
            const uint32_t bb = sbase + (BBO + buf * 5120) * 4;
#pragma unroll
            for (int t = 0; t < 2; t++) {         // A: 512 cp16
                int o = tid + 256 * t, m = o >> 2, q = o & 3;
                cp16(ab + (m * 20 + q * 4) * 4, A + (size_t)(m0 + m) * 512 + kc + q * 8);
            }
#pragma unroll
            for (int j = 0; j < 4; j++) {         // B: 1024 cp16
                int o = tid + 256 * j, n = o >> 2, q = o & 3;
                cp16(bb + (n * 20 + q * 4) * 4, W + (size_t)(n0s + n) * 512 + kc + q * 8);
            }
        }
        asm volatile("cp.async.commit_group;");
    };

    float acc[4][8][4];
#pragma unroll
    for (int mb = 0; mb < 4; mb++)
#pragma unroll
        for (int nb = 0; nb < 8; nb++)
#pragma unroll
            for (int r = 0; r < 4; r++) acc[mb][nb][r] = 0.f;
    float s[8];
#pragma unroll
    for (int i = 0; i < 8; i++) s[i] = 0.f;

    issue(0); issue(1);

    for (int c = 0; c < NC; c++) {
        asm volatile("cp.async.wait_group 1;");
        __syncthreads();          // chunk c landed; everyone done computing c-1
        issue(c + 2);

        const int buf = c % 3;
        const uint32_t* As = smu + ABO + buf * 2560;
        const uint32_t* Bs = smu + BBO + buf * 5120;
#pragma unroll
        for (int ks = 0; ks < 2; ks++) {          // two K=16 steps
            const int base = ks * 8 + lq;
            uint32_t afr[4][4], bfr[8][2];
#pragma unroll
            for (int mb = 0; mb < 4; mb++) {
                int r = wm * 64 + mb * 16 + lg;
                afr[mb][0] = As[r * 20 + base];
                afr[mb][1] = As[(r + 8) * 20 + base];
                afr[mb][2] = As[r * 20 + base + 4];
                afr[mb][3] = As[(r + 8) * 20 + base + 4];
            }
#pragma unroll
            for (int nb = 0; nb < 8; nb++) {
                int n = wn * 64 + nb * 8 + lg;
                bfr[nb][0] = Bs[n * 20 + base];
                bfr[nb][1] = Bs[n * 20 + base + 4];
            }
#pragma unroll
            for (int mb = 0; mb < 4; mb++)
#pragma unroll
                for (int nb = 0; nb < 8; nb++)
                    MMA_F16(acc[mb][nb], afr[mb], bfr[nb]);
        }

        // ---- per-column-pass fused epilogue ----
        if ((c & 15) == 15) {
            const int n0 = (c >> 4) << 8;
#pragma unroll
            for (int mb = 0; mb < 4; mb++)
#pragma unroll
                for (int nb = 0; nb < 8; nb++) {
                    int col = n0 + wn * 64 + nb * 8 + lq * 2;
#pragma unroll
                    for (int r = 0; r < 4; r++) {
                        int cc = col + (r & 1);
                        float av = acc[mb][nb][r];
                        float t1 = fast_tanh(av + so1[cc]);
                        float val;
                        if (DUAL) {
                            float t2 = fast_tanh(av + so2[cc]);
                            val = sv[cc] * (5.f * t1 + t2);
                        } else {
                            val = sv[cc] * t1;
                        }
                        s[mb * 2 + (r >> 1)] += val;
                        acc[mb][nb][r] = 0.f;
                    }
                }
        }
    }

    // ---- final reduction: quad shuffle, cross-warp smem ----
#pragma unroll
    for (int i = 0; i < 8; i++) {
        s[i] += __shfl_xor_sync(0xffffffffu, s[i], 1);
        s[i] += __shfl_xor_sync(0xffffffffu, s[i], 2);
    }
    float* red = (float*)(smu + RED);
    if (lq == 0) {
#pragma unroll
        for (int i = 0; i < 8; i++) {
            int row = wm * 64 + (i >> 1) * 16 + (i & 1) * 8 + lg;
            red[row * 4 + wn] = s[i];
        }
    }
    __syncthreads();
    if (tid < 128) {
        float* rr = red + tid * 4;
        out[m0 + tid] = rr[0] + rr[1] + rr[2] + rr[3];
    }
}

// ---------------- small NT GEMM: warp per output element ----------------
__global__ void small_gemm(const float* __restrict__ A, int lda,
                           const float* __restrict__ W, int ldw,
                           const float* __restrict__ Cinit,
                           float* __restrict__ C, int N)
{
    int m = blockIdx.y;
    int n = blockIdx.x * 8 + (threadIdx.x >> 5);
    int lane = threadIdx.x & 31;
    if (n >= N) return;
    const float* a = A + (size_t)m * lda;
    const float* w = W + (size_t)n * ldw;
    float sum = 0.f;
#pragma unroll
    for (int c = 0; c < 4; c++) {
        int k = c * 128 + lane * 4;
        float4 av = *(const float4*)(a + k);
        float4 wv = *(const float4*)(w + k);
        sum += av.x*wv.x + av.y*wv.y + av.z*wv.z + av.w*wv.w;
    }
#pragma unroll
    for (int o = 16; o; o >>= 1) sum += __shfl_xor_sync(0xffffffffu, sum, o);
    if (lane == 0) {
        float base = Cinit ? Cinit[(size_t)m * N + n] : 0.f;
        C[(size_t)m * N + n] = base + sum;
    }
}

// ---------------- GRU gates ----------------
__global__ void gru_gate(const float* __restrict__ bih, const float* __restrict__ bhh,
                         const float* __restrict__ hprev, float* __restrict__ hnew)
{
    int b = blockIdx.x, h = threadIdx.x;
    const float* gx = g_gx + b * 1536;
    const float* gh = g_gh + b * 1536;
    float r = 1.f / (1.f + expf(-(gx[h]     + bih[h]     + gh[h]     + bhh[h])));
    float z = 1.f / (1.f + expf(-(gx[512+h] + bih[512+h] + gh[512+h] + bhh[512+h])));
    float n = tanhf(gx[1024+h] + bih[1024+h] + r * (gh[1024+h] + bhh[1024+h]));
    float hp = hprev[b*512 + h];
    hnew[b*512 + h] = (1.f - z) * n + z * hp;
}

// ---------------- softmax over N=512 (in place), one row per block ----------------
__global__ void softmax512(float* __restrict__ data)
{
    int row = blockIdx.x;
    float* p = data + (size_t)row * 512;
    int tid = threadIdx.x; // 256
    float v0 = p[tid], v1 = p[tid + 256];
    __shared__ float sm[8];
    float mx = fmaxf(v0, v1);
#pragma unroll
    for (int o = 16; o; o >>= 1) mx = fmaxf(mx, __shfl_xor_sync(0xffffffffu, mx, o));
    if ((tid & 31) == 0) sm[tid >> 5] = mx;
    __syncthreads();
    float m = sm[0];
#pragma unroll
    for (int i = 1; i < 8; i++) m = fmaxf(m, sm[i]);
    float e0 = expf(v0 - m), e1 = expf(v1 - m);
    __syncthreads();
    float ss = e0 + e1;
#pragma unroll
    for (int o = 16; o; o >>= 1) ss += __shfl_xor_sync(0xffffffffu, ss, o);
    if ((tid & 31) == 0) sm[tid >> 5] = ss;
    __syncthreads();
    float tot = sm[0]+sm[1]+sm[2]+sm[3]+sm[4]+sm[5]+sm[6]+sm[7];
    float inv = 1.f / tot;
    p[tid] = e0 * inv;
    p[tid + 256] = e1 * inv;
}

// ---------------- both contexts in one pass over static_hidden ----------------
__global__ void context_kernel(const float* __restrict__ sh,
                               const float* __restrict__ attn, // [2*B][512]
                               float* __restrict__ ctx, float* __restrict__ ctxt)
{
    int b = blockIdx.x;
    int h = threadIdx.x; // 512
    __shared__ float ae[512], at[512];
    ae[h] = attn[b*512 + h];
    at[h] = attn[65536 + b*512 + h];
    __syncthreads();
    const float* sp = sh + (size_t)b * 512 * 512 + h;
    float ce = 0.f, ctv = 0.f;
#pragma unroll 4
    for (int n = 0; n < 512; n++) {
        float sv2 = sp[(size_t)n * 512];
        ce  = fmaf(ae[n], sv2, ce);
        ctv = fmaf(at[n], sv2, ctv);
    }
    ctx[b*512 + h] = ce;
    ctxt[b*512 + h] = ctv;
}

// ---------------- host ----------------
static void* sym_addr(const void* s)
{
    void* p = nullptr;
    cudaGetSymbolAddress(&p, s);
    return p;
}

extern "C" void kernel_launch(void* const* d_in, const int* in_sizes, int n_in,
                              void* d_out, int out_size)
{
    const float* static_h  = (const float*)d_in[0];
    const float* state_emb = (const float*)d_in[1];
    const float* dec_h     = (const float*)d_in[2];
    const float* tgt_h     = (const float*)d_in[3];
    const float* last_hh   = (const float*)d_in[4];
    const float* ptr_v     = (const float*)d_in[5];
    const float* ptr_W     = (const float*)d_in[6];
    const float* enc_v     = (const float*)d_in[7];
    const float* enc_W     = (const float*)d_in[8];
    const float* tgt_v     = (const float*)d_in[9];
    const float* tgt_W     = (const float*)d_in[10];
    const float* w_ih      = (const float*)d_in[11];
    const float* w_hh      = (const float*)d_in[12];
    const float* b_ih      = (const float*)d_in[13];
    const float* b_hh      = (const float*)d_in[14];

    float* out  = (float*)d_out;        // probs: [0, 65536)
    float* hnew = out + 65536;          // new_last_hh: [65536, 131072)

    float* p_gx      = (float*)sym_addr(g_gx);
    float* p_gh      = (float*)sym_addr(g_gh);
    float* p_off_enc = (float*)sym_addr(g_off_enc);
    float* p_off_tgt = (float*)sym_addr(g_off_tgt);
    float* p_off_st  = (float*)sym_addr(g_off_state);
    float* p_offP    = (float*)sym_addr(g_offP);
    float* p_offPt   = (float*)sym_addr(g_offPt);
    float* p_scores  = (float*)sym_addr(g_scores);
    float* p_ctx     = (float*)sym_addr(g_ctx);
    float* p_ctxt    = (float*)sym_addr(g_ctxt);
    __half* p_Ah     = (__half*)sym_addr(g_Ah);
    __half* p_Wenc   = (__half*)sym_addr(g_Wenc);
    __half* p_Wtgt   = (__half*)sym_addr(g_Wtgt);
    __half* p_Wptr   = (__half*)sym_addr(g_Wptr);

    constexpr int SMEM_BYTES = 25088 * 4;   // ~98 KB
    cudaFuncSetAttribute(tc_mma<false>, cudaFuncAttributeMaxDynamicSharedMemorySize, SMEM_BYTES);
    cudaFuncSetAttribute(tc_mma<true>,  cudaFuncAttributeMaxDynamicSharedMemorySize, SMEM_BYTES);

    dim3 g192(192, 128), g64(64, 128);

    // fp16 conversion (rn — unbiased)
    f2h_a<<<16384, 256>>>(static_h, p_Ah);
    f2h_w<<<512, 64>>>(enc_W, 1024, p_Wenc);
    f2h_w<<<512, 64>>>(tgt_W, 1024, p_Wtgt);
    f2h_w<<<512, 64>>>(ptr_W, 1536, p_Wptr);

    // GRU pre-activations + independent offsets (exact fp32)
    small_gemm<<<g192, 256>>>(dec_h,   512, w_ih, 512, nullptr, p_gx, 1536);
    small_gemm<<<g192, 256>>>(last_hh, 512, w_hh, 512, nullptr, p_gh, 1536);
    small_gemm<<<g64, 256>>>(tgt_h,     512, tgt_W + 512,  1024, nullptr, p_off_tgt, 512);
    small_gemm<<<g64, 256>>>(state_emb, 512, ptr_W + 1024, 1536, nullptr, p_off_st,  512);
    gru_gate<<<128, 512>>>(b_ih, b_hh, last_hh, hnew);
    small_gemm<<<g64, 256>>>(hnew,      512, enc_W + 512,  1024, nullptr, p_off_enc, 512);

    // big tensor-core GEMMs: fused attention scores
    tc_mma<false><<<512, 256, SMEM_BYTES>>>(p_Ah, p_Wenc, p_off_enc, nullptr, enc_v, p_scores);
    tc_mma<false><<<512, 256, SMEM_BYTES>>>(p_Ah, p_Wtgt, p_off_tgt, nullptr, tgt_v, p_scores + 65536);

    // softmax both attentions, then both contexts in one static pass
    softmax512<<<256, 256>>>(p_scores);
    context_kernel<<<128, 512>>>(static_h, p_scores, p_ctx, p_ctxt);

    // pointer offsets (context part + state part)
    small_gemm<<<g64, 256>>>(p_ctx,  512, ptr_W + 512, 1536, p_off_st, p_offP,  512);
    small_gemm<<<g64, 256>>>(p_ctxt, 512, ptr_W + 512, 1536, p_off_st, p_offPt, 512);

    // final fused pointer GEMM: 5*tanh(S+offP) + tanh(S+offPt), dot ptr_v
    tc_mma<true><<<512, 256, SMEM_BYTES>>>(p_Ah, p_Wptr, p_offP, p_offPt, ptr_v, out);
}

// round 6
// speedup vs baseline: 4.4595x; 1.0060x over previous
#include <cuda_runtime.h>
#include <cuda_fp16.h>
#include <math.h>
#include <cstdint>

#define B_ 128
#define N_ 512
#define H_ 512
#define M_ (B_*N_)   // 65536

// ---------------- scratch (static device allocations) ----------------
__device__ float g_gx[B_*3*H_];
__device__ float g_gh[B_*3*H_];
__device__ float g_off_enc[B_*H_];
__device__ float g_off_tgt[B_*H_];
__device__ float g_off_state[B_*H_];
__device__ float g_offP[B_*H_];
__device__ float g_offPt[B_*H_];
__device__ float g_scores[2*B_*N_];      // enc rows 0..127, tgt rows 128..255
__device__ float g_ctx[B_*H_];
__device__ float g_ctxt[B_*H_];
__device__ __half g_Ah[(size_t)M_*H_];   // 64 MB: fp16 static_hidden
__device__ __half g_Wenc[H_*H_];         // fp16 static halves (ld = 512)
__device__ __half g_Wtgt[H_*H_];
__device__ __half g_Wptr[H_*H_];

// ---------------- helpers ----------------
__device__ __forceinline__ uint32_t smem_u32(const void* p) {
    uint32_t a;
    asm("{ .reg .u64 t; cvta.to.shared.u64 t, %1; cvt.u32.u64 %0, t; }" : "=r"(a) : "l"(p));
    return a;
}
__device__ __forceinline__ void cp16(uint32_t dst, const void* src) {
    asm volatile("cp.async.cg.shared.global [%0], [%1], 16;" :: "r"(dst), "l"(src));
}
__device__ __forceinline__ float fast_tanh(float x) {
    float r;
    asm("tanh.approx.f32 %0, %1;" : "=f"(r) : "f"(x));
    return r;
}
__device__ __forceinline__ uint32_t h2u(__half2 h) {
    uint32_t u;
    memcpy(&u, &h, 4);
    return u;
}
__device__ __forceinline__ void ldsm4(uint32_t& r0, uint32_t& r1, uint32_t& r2, uint32_t& r3,
                                      uint32_t addr) {
    asm volatile("ldmatrix.sync.aligned.m8n8.x4.shared.b16 {%0,%1,%2,%3}, [%4];"
                 : "=r"(r0), "=r"(r1), "=r"(r2), "=r"(r3) : "r"(addr));
}
#define MMA_F16(c, a, b) \
    asm volatile("mma.sync.aligned.m16n8k16.row.col.f32.f16.f16.f32 " \
        "{%0,%1,%2,%3}, {%4,%5,%6,%7}, {%8,%9}, {%0,%1,%2,%3};" \
        : "+f"((c)[0]), "+f"((c)[1]), "+f"((c)[2]), "+f"((c)[3]) \
        : "r"((a)[0]), "r"((a)[1]), "r"((a)[2]), "r"((a)[3]), \
          "r"((b)[0]), "r"((b)[1]))

// ---------------- fp32 -> fp16 conversion kernels ----------------
__global__ void f2h_a(const float* __restrict__ in, __half* __restrict__ out)
{
    size_t i = (size_t)blockIdx.x * blockDim.x + threadIdx.x;  // 8 floats per thread
    const float4* in4 = (const float4*)in;
    float4 f0 = in4[2*i], f1 = in4[2*i + 1];
    uint4 u = make_uint4(h2u(__floats2half2_rn(f0.x, f0.y)),
                         h2u(__floats2half2_rn(f0.z, f0.w)),
                         h2u(__floats2half2_rn(f1.x, f1.y)),
                         h2u(__floats2half2_rn(f1.z, f1.w)));
    ((uint4*)out)[i] = u;
}
__global__ void f2h_w(const float* __restrict__ W, int ldw, __half* __restrict__ out)
{
    int n = blockIdx.x, t = threadIdx.x;  // 64 threads x 8 floats
    const float4* row = (const float4*)(W + (size_t)n * ldw);
    float4 f0 = row[2*t], f1 = row[2*t + 1];
    uint4 u = make_uint4(h2u(__floats2half2_rn(f0.x, f0.y)),
                         h2u(__floats2half2_rn(f0.z, f0.w)),
                         h2u(__floats2half2_rn(f1.x, f1.y)),
                         h2u(__floats2half2_rn(f1.z, f1.w)));
    ((uint4*)(out + (size_t)n * 512))[t] = u;
}

// ================= tensor-core GEMM (mma.sync f16, f32 accum) + fused tanh-dot ==========
// Per CTA: rows [m0, m0+128) x all 512 cols of A @ W^T (K=512), two column passes of 256.
// DUAL=0: out[m] = sum_h v[h] * tanh(acc + off1[b,h])
// DUAL=1: out[m] = sum_h v[h] * (5*tanh(acc + off1[b,h]) + tanh(acc + off2[b,h]))
// smem u32 map: [0,512) v | [512,1024) off1 | [1024,1536) off2 | [1536,2048) red
//               [2048,9728) A bufs 3 x 128 x 20 | [9728,25088) B bufs 3 x 256 x 20
template<bool DUAL>
__global__ void __launch_bounds__(256, 1)
tc_mma(const __half* __restrict__ A,     // ld = 512
       const __half* __restrict__ W,     // ld = 512
       const float* __restrict__ off1,
       const float* __restrict__ off2,
       const float* __restrict__ v,
       float* __restrict__ out)
{
    extern __shared__ uint32_t smu[];
    const uint32_t sbase = smem_u32(smu);
    const int tid = threadIdx.x;
    const int wid = tid >> 5, lane = tid & 31;
    const int wm = wid & 1, wn = wid >> 1;       // warp tile 64(M) x 64(N); CTA 128 x 256
    const int lq = lane & 3, lg = lane >> 2;
    const int m0 = blockIdx.x << 7;
    const int b  = m0 >> 9;

    constexpr int SV = 0, SO1 = 512, SO2 = 1024, RED = 1536;
    constexpr int ABO = 2048, BBO = 9728;
    constexpr int NC = 32;                        // 2 col-passes x 16 K32-chunks

    float* sv  = (float*)(smu + SV);
    float* so1 = (float*)(smu + SO1);
    float* so2 = (float*)(smu + SO2);
    for (int i = tid; i < 512; i += 256) {
        sv[i]  = v[i];
        so1[i] = off1[b * 512 + i];
        if (DUAL) so2[i] = off2[b * 512 + i];
    }

    // ldmatrix per-lane base offsets (bytes)
    const int lt = lane >> 3, lj = lane & 7;
    const uint32_t a_lane = ((wm * 64 + (lt & 1) * 8 + lj) * 20 + (lt >> 1) * 4) * 4;
    const uint32_t b_lane = ((wn * 64 + (lt >> 1) * 8 + lj) * 20 + (lt & 1) * 4) * 4;

    // chunk c: k = (c&15)*32, n-pass = c>>4; buffer c%3
    auto issue = [&](int c) {
        if (c < NC) {
            const int buf = c % 3;
            const int kc  = (c & 15) << 5;        // in halves
            const int n0s = (c >> 4) << 8;
            const uint32_t ab = sbase + (ABO + buf * 2560) * 4;
            const uint32_t bb = sbase + (BBO + buf * 5120) * 4;
#pragma unroll
            for (int t = 0; t < 2; t++) {         // A: 512 cp16
                int o = tid + 256 * t, m = o >> 2, q = o & 3;
                cp16(ab + (m * 20 + q * 4) * 4, A + (size_t)(m0 + m) * 512 + kc + q * 8);
            }
#pragma unroll
            for (int j = 0; j < 4; j++) {         // B: 1024 cp16
                int o = tid + 256 * j, n = o >> 2, q = o & 3;
                cp16(bb + (n * 20 + q * 4) * 4, W + (size_t)(n0s + n) * 512 + kc + q * 8);
            }
        }
        asm volatile("cp.async.commit_group;");
    };

    float acc[4][8][4];
#pragma unroll
    for (int mb = 0; mb < 4; mb++)
#pragma unroll
        for (int nb = 0; nb < 8; nb++)
#pragma unroll
            for (int r = 0; r < 4; r++) acc[mb][nb][r] = 0.f;
    float s[8];
#pragma unroll
    for (int i = 0; i < 8; i++) s[i] = 0.f;

    issue(0); issue(1);

    for (int c = 0; c < NC; c++) {
        asm volatile("cp.async.wait_group 1;");
        __syncthreads();          // chunk c landed; everyone done computing c-1
        issue(c + 2);

        const int buf = c % 3;
        const uint32_t abuf = sbase + (ABO + buf * 2560) * 4 + a_lane;
        const uint32_t bbuf = sbase + (BBO + buf * 5120) * 4 + b_lane;
#pragma unroll
        for (int ks = 0; ks < 2; ks++) {          // two K=16 steps
            uint32_t afr[4][4], bfr[8][2];
#pragma unroll
            for (int mb = 0; mb < 4; mb++)
                ldsm4(afr[mb][0], afr[mb][1], afr[mb][2], afr[mb][3],
                      abuf + (mb * 320 + ks * 8) * 4);
#pragma unroll
            for (int p = 0; p < 4; p++)
                ldsm4(bfr[2*p][0], bfr[2*p][1], bfr[2*p+1][0], bfr[2*p+1][1],
                      bbuf + (p * 320 + ks * 8) * 4);
#pragma unroll
            for (int mb = 0; mb < 4; mb++)
#pragma unroll
                for (int nb = 0; nb < 8; nb++)
                    MMA_F16(acc[mb][nb], afr[mb], bfr[nb]);
        }

        // ---- per-column-pass fused epilogue ----
        if ((c & 15) == 15) {
            const int n0 = (c >> 4) << 8;
#pragma unroll
            for (int mb = 0; mb < 4; mb++)
#pragma unroll
                for (int nb = 0; nb < 8; nb++) {
                    int col = n0 + wn * 64 + nb * 8 + lq * 2;
#pragma unroll
                    for (int r = 0; r < 4; r++) {
                        int cc = col + (r & 1);
                        float av = acc[mb][nb][r];
                        float t1 = fast_tanh(av + so1[cc]);
                        float val;
                        if (DUAL) {
                            float t2 = fast_tanh(av + so2[cc]);
                            val = sv[cc] * (5.f * t1 + t2);
                        } else {
                            val = sv[cc] * t1;
                        }
                        s[mb * 2 + (r >> 1)] += val;
                        acc[mb][nb][r] = 0.f;
                    }
                }
        }
    }

    // ---- final reduction: quad shuffle, cross-warp smem ----
#pragma unroll
    for (int i = 0; i < 8; i++) {
        s[i] += __shfl_xor_sync(0xffffffffu, s[i], 1);
        s[i] += __shfl_xor_sync(0xffffffffu, s[i], 2);
    }
    float* red = (float*)(smu + RED);
    if (lq == 0) {
#pragma unroll
        for (int i = 0; i < 8; i++) {
            int row = wm * 64 + (i >> 1) * 16 + (i & 1) * 8 + lg;
            red[row * 4 + wn] = s[i];
        }
    }
    __syncthreads();
    if (tid < 128) {
        float* rr = red + tid * 4;
        out[m0 + tid] = rr[0] + rr[1] + rr[2] + rr[3];
    }
}

// ---------------- small NT GEMM: warp per output element ----------------
__global__ void small_gemm(const float* __restrict__ A, int lda,
                           const float* __restrict__ W, int ldw,
                           const float* __restrict__ Cinit,
                           float* __restrict__ C, int N)
{
    int m = blockIdx.y;
    int n = blockIdx.x * 8 + (threadIdx.x >> 5);
    int lane = threadIdx.x & 31;
    if (n >= N) return;
    const float* a = A + (size_t)m * lda;
    const float* w = W + (size_t)n * ldw;
    float sum = 0.f;
#pragma unroll
    for (int c = 0; c < 4; c++) {
        int k = c * 128 + lane * 4;
        float4 av = *(const float4*)(a + k);
        float4 wv = *(const float4*)(w + k);
        sum += av.x*wv.x + av.y*wv.y + av.z*wv.z + av.w*wv.w;
    }
#pragma unroll
    for (int o = 16; o; o >>= 1) sum += __shfl_xor_sync(0xffffffffu, sum, o);
    if (lane == 0) {
        float base = Cinit ? Cinit[(size_t)m * N + n] : 0.f;
        C[(size_t)m * N + n] = base + sum;
    }
}

// ---------------- GRU gates ----------------
__global__ void gru_gate(const float* __restrict__ bih, const float* __restrict__ bhh,
                         const float* __restrict__ hprev, float* __restrict__ hnew)
{
    int b = blockIdx.x, h = threadIdx.x;
    const float* gx = g_gx + b * 1536;
    const float* gh = g_gh + b * 1536;
    float r = 1.f / (1.f + expf(-(gx[h]     + bih[h]     + gh[h]     + bhh[h])));
    float z = 1.f / (1.f + expf(-(gx[512+h] + bih[512+h] + gh[512+h] + bhh[512+h])));
    float n = tanhf(gx[1024+h] + bih[1024+h] + r * (gh[1024+h] + bhh[1024+h]));
    float hp = hprev[b*512 + h];
    hnew[b*512 + h] = (1.f - z) * n + z * hp;
}

// ---------------- softmax over N=512 (in place), one row per block ----------------
__global__ void softmax512(float* __restrict__ data)
{
    int row = blockIdx.x;
    float* p = data + (size_t)row * 512;
    int tid = threadIdx.x; // 256
    float v0 = p[tid], v1 = p[tid + 256];
    __shared__ float sm[8];
    float mx = fmaxf(v0, v1);
#pragma unroll
    for (int o = 16; o; o >>= 1) mx = fmaxf(mx, __shfl_xor_sync(0xffffffffu, mx, o));
    if ((tid & 31) == 0) sm[tid >> 5] = mx;
    __syncthreads();
    float m = sm[0];
#pragma unroll
    for (int i = 1; i < 8; i++) m = fmaxf(m, sm[i]);
    float e0 = expf(v0 - m), e1 = expf(v1 - m);
    __syncthreads();
    float ss = e0 + e1;
#pragma unroll
    for (int o = 16; o; o >>= 1) ss += __shfl_xor_sync(0xffffffffu, ss, o);
    if ((tid & 31) == 0) sm[tid >> 5] = ss;
    __syncthreads();
    float tot = sm[0]+sm[1]+sm[2]+sm[3]+sm[4]+sm[5]+sm[6]+sm[7];
    float inv = 1.f / tot;
    p[tid] = e0 * inv;
    p[tid + 256] = e1 * inv;
}

// ---------------- both contexts in one pass over static_hidden ----------------
__global__ void context_kernel(const float* __restrict__ sh,
                               const float* __restrict__ attn, // [2*B][512]
                               float* __restrict__ ctx, float* __restrict__ ctxt)
{
    int b = blockIdx.x;
    int h = threadIdx.x; // 512
    __shared__ float ae[512], at[512];
    ae[h] = attn[b*512 + h];
    at[h] = attn[65536 + b*512 + h];
    __syncthreads();
    const float* sp = sh + (size_t)b * 512 * 512 + h;
    float ce = 0.f, ctv = 0.f;
#pragma unroll 4
    for (int n = 0; n < 512; n++) {
        float sv2 = sp[(size_t)n * 512];
        ce  = fmaf(ae[n], sv2, ce);
        ctv = fmaf(at[n], sv2, ctv);
    }
    ctx[b*512 + h] = ce;
    ctxt[b*512 + h] = ctv;
}

// ---------------- host ----------------
static void* sym_addr(const void* s)
{
    void* p = nullptr;
    cudaGetSymbolAddress(&p, s);
    return p;
}

extern "C" void kernel_launch(void* const* d_in, const int* in_sizes, int n_in,
                              void* d_out, int out_size)
{
    const float* static_h  = (const float*)d_in[0];
    const float* state_emb = (const float*)d_in[1];
    const float* dec_h     = (const float*)d_in[2];
    const float* tgt_h     = (const float*)d_in[3];
    const float* last_hh   = (const float*)d_in[4];
    const float* ptr_v     = (const float*)d_in[5];
    const float* ptr_W     = (const float*)d_in[6];
    const float* enc_v     = (const float*)d_in[7];
    const float* enc_W     = (const float*)d_in[8];
    const float* tgt_v     = (const float*)d_in[9];
    const float* tgt_W     = (const float*)d_in[10];
    const float* w_ih      = (const float*)d_in[11];
    const float* w_hh      = (const float*)d_in[12];
    const float* b_ih      = (const float*)d_in[13];
    const float* b_hh      = (const float*)d_in[14];

    float* out  = (float*)d_out;        // probs: [0, 65536)
    float* hnew = out + 65536;          // new_last_hh: [65536, 131072)

    float* p_gx      = (float*)sym_addr(g_gx);
    float* p_gh      = (float*)sym_addr(g_gh);
    float* p_off_enc = (float*)sym_addr(g_off_enc);
    float* p_off_tgt = (float*)sym_addr(g_off_tgt);
    float* p_off_st  = (float*)sym_addr(g_off_state);
    float* p_offP    = (float*)sym_addr(g_offP);
    float* p_offPt   = (float*)sym_addr(g_offPt);
    float* p_scores  = (float*)sym_addr(g_scores);
    float* p_ctx     = (float*)sym_addr(g_ctx);
    float* p_ctxt    = (float*)sym_addr(g_ctxt);
    __half* p_Ah     = (__half*)sym_addr(g_Ah);
    __half* p_Wenc   = (__half*)sym_addr(g_Wenc);
    __half* p_Wtgt   = (__half*)sym_addr(g_Wtgt);
    __half* p_Wptr   = (__half*)sym_addr(g_Wptr);

    constexpr int SMEM_BYTES = 25088 * 4;   // ~98 KB
    cudaFuncSetAttribute(tc_mma<false>, cudaFuncAttributeMaxDynamicSharedMemorySize, SMEM_BYTES);
    cudaFuncSetAttribute(tc_mma<true>,  cudaFuncAttributeMaxDynamicSharedMemorySize, SMEM_BYTES);

    dim3 g192(192, 128), g64(64, 128);

    // ---- launches 1-5 (so launch 6 = tc_mma<false> tgt, captured by ncu -s 5 -c 1) ----
    f2h_a<<<16384, 256>>>(static_h, p_Ah);                                           // 1
    f2h_w<<<512, 64>>>(tgt_W, 1024, p_Wtgt);                                         // 2
    small_gemm<<<g64, 256>>>(tgt_h, 512, tgt_W + 512, 1024, nullptr, p_off_tgt, 512);// 3
    f2h_w<<<512, 64>>>(enc_W, 1024, p_Wenc);                                         // 4
    f2h_w<<<512, 64>>>(ptr_W, 1536, p_Wptr);                                         // 5

    // ---- launch 6: big tgt GEMM (profiled) ----
    tc_mma<false><<<512, 256, SMEM_BYTES>>>(p_Ah, p_Wtgt, p_off_tgt, nullptr, tgt_v,
                                            p_scores + 65536);                      // 6

    // GRU chain + enc offset
    small_gemm<<<g192, 256>>>(dec_h,   512, w_ih, 512, nullptr, p_gx, 1536);         // 7
    small_gemm<<<g192, 256>>>(last_hh, 512, w_hh, 512, nullptr, p_gh, 1536);         // 8
    gru_gate<<<128, 512>>>(b_ih, b_hh, last_hh, hnew);                               // 9
    small_gemm<<<g64, 256>>>(hnew, 512, enc_W + 512, 1024, nullptr, p_off_enc, 512); // 10

    // big enc GEMM
    tc_mma<false><<<512, 256, SMEM_BYTES>>>(p_Ah, p_Wenc, p_off_enc, nullptr, enc_v,
                                            p_scores);                               // 11

    small_gemm<<<g64, 256>>>(state_emb, 512, ptr_W + 1024, 1536, nullptr, p_off_st, 512); // 12

    // softmax both attentions, then both contexts in one static pass
    softmax512<<<256, 256>>>(p_scores);                                              // 13
    context_kernel<<<128, 512>>>(static_h, p_scores, p_ctx, p_ctxt);                 // 14

    // pointer offsets (context part + state part)
    small_gemm<<<g64, 256>>>(p_ctx,  512, ptr_W + 512, 1536, p_off_st, p_offP,  512);// 15
    small_gemm<<<g64, 256>>>(p_ctxt, 512, ptr_W + 512, 1536, p_off_st, p_offPt, 512);// 16

    // final fused pointer GEMM: 5*tanh(S+offP) + tanh(S+offPt), dot ptr_v
    tc_mma<true><<<512, 256, SMEM_BYTES>>>(p_Ah, p_Wptr, p_offP, p_offPt, ptr_v, out); // 17
}

// round 7
// speedup vs baseline: 5.1276x; 1.1498x over previous
#include <cuda_runtime.h>
#include <cuda_fp16.h>
#include <math.h>
#include <cstdint>

#define B_ 128
#define N_ 512
#define H_ 512
#define M_ (B_*N_)   // 65536

// ---------------- scratch (static device allocations) ----------------
__device__ float g_gx[B_*3*H_];
__device__ float g_gh[B_*3*H_];
__device__ float g_off_enc[B_*H_];
__device__ float g_off_tgt[B_*H_];
__device__ float g_off_state[B_*H_];
__device__ float g_offP[B_*H_];
__device__ float g_offPt[B_*H_];
__device__ float g_scores[2*B_*N_];      // enc rows 0..127, tgt rows 128..255
__device__ float g_ctx[B_*H_];
__device__ float g_ctxt[B_*H_];
__device__ __half g_Ah[(size_t)M_*H_];   // 64 MB: fp16 static_hidden
__device__ __half g_Wenc[H_*H_];         // fp16 static halves (ld = 512)
__device__ __half g_Wtgt[H_*H_];
__device__ __half g_Wptr[H_*H_];

// ---------------- helpers ----------------
__device__ __forceinline__ uint32_t smem_u32(const void* p) {
    uint32_t a;
    asm("{ .reg .u64 t; cvta.to.shared.u64 t, %1; cvt.u32.u64 %0, t; }" : "=r"(a) : "l"(p));
    return a;
}
__device__ __forceinline__ void cp16(uint32_t dst, const void* src) {
    asm volatile("cp.async.cg.shared.global [%0], [%1], 16;" :: "r"(dst), "l"(src));
}
__device__ __forceinline__ float fast_tanh(float x) {
    float r;
    asm("tanh.approx.f32 %0, %1;" : "=f"(r) : "f"(x));
    return r;
}
__device__ __forceinline__ uint32_t h2u(__half2 h) {
    uint32_t u;
    memcpy(&u, &h, 4);
    return u;
}
__device__ __forceinline__ void ldsm4(uint32_t& r0, uint32_t& r1, uint32_t& r2, uint32_t& r3,
                                      uint32_t addr) {
    asm volatile("ldmatrix.sync.aligned.m8n8.x4.shared.b16 {%0,%1,%2,%3}, [%4];"
                 : "=r"(r0), "=r"(r1), "=r"(r2), "=r"(r3) : "r"(addr));
}
#define MMA_F16(c, a, b) \
    asm volatile("mma.sync.aligned.m16n8k16.row.col.f32.f16.f16.f32 " \
        "{%0,%1,%2,%3}, {%4,%5,%6,%7}, {%8,%9}, {%0,%1,%2,%3};" \
        : "+f"((c)[0]), "+f"((c)[1]), "+f"((c)[2]), "+f"((c)[3]) \
        : "r"((a)[0]), "r"((a)[1]), "r"((a)[2]), "r"((a)[3]), \
          "r"((b)[0]), "r"((b)[1]))

// ---------------- fp32 -> fp16 conversion kernels ----------------
__global__ void f2h_a(const float* __restrict__ in, __half* __restrict__ out)
{
    size_t i = (size_t)blockIdx.x * blockDim.x + threadIdx.x;  // 8 floats per thread
    const float4* in4 = (const float4*)in;
    float4 f0 = in4[2*i], f1 = in4[2*i + 1];
    uint4 u = make_uint4(h2u(__floats2half2_rn(f0.x, f0.y)),
                         h2u(__floats2half2_rn(f0.z, f0.w)),
                         h2u(__floats2half2_rn(f1.x, f1.y)),
                         h2u(__floats2half2_rn(f1.z, f1.w)));
    ((uint4*)out)[i] = u;
}
__global__ void f2h_w(const float* __restrict__ W, int ldw, __half* __restrict__ out)
{
    int n = blockIdx.x, t = threadIdx.x;  // 64 threads x 8 floats
    const float4* row = (const float4*)(W + (size_t)n * ldw);
    float4 f0 = row[2*t], f1 = row[2*t + 1];
    uint4 u = make_uint4(h2u(__floats2half2_rn(f0.x, f0.y)),
                         h2u(__floats2half2_rn(f0.z, f0.w)),
                         h2u(__floats2half2_rn(f1.x, f1.y)),
                         h2u(__floats2half2_rn(f1.z, f1.w)));
    ((uint4*)(out + (size_t)n * 512))[t] = u;
}

// ================= tensor-core GEMM (mma.sync f16, f32 accum) + fused tanh-dot ==========
// CTA: 64(M) x 512(N), K=512; 512 threads, 16 warps, warp tile 32x64.
// DUAL=0: out[m] = sum_h v[h] * tanh(acc + off1[b,h])
// DUAL=1: out[m] = sum_h v[h] * (5*tanh(acc + off1[b,h]) + tanh(acc + off2[b,h]))
// smem u32: [0,512) v | [512,1024) off1 | [1024,1536) off2 | [1536,2048) red(64x8)
//           [2048,5888) A bufs 3 x 64 x 20 | [5888,36608) B bufs 3 x 512 x 20
template<bool DUAL>
__global__ void __launch_bounds__(512, 1)
tc_mma(const __half* __restrict__ A,     // ld = 512
       const __half* __restrict__ W,     // ld = 512
       const float* __restrict__ off1,
       const float* __restrict__ off2,
       const float* __restrict__ v,
       float* __restrict__ out)
{
    extern __shared__ uint32_t smu[];
    const uint32_t sbase = smem_u32(smu);
    const int tid = threadIdx.x;
    const int wid = tid >> 5, lane = tid & 31;
    const int wm = wid & 1, wn = wid >> 1;       // warp tile 32(M) x 64(N)
    const int lq = lane & 3, lg = lane >> 2;
    const int m0 = blockIdx.x << 6;
    const int b  = m0 >> 9;

    constexpr int SV = 0, SO1 = 512, SO2 = 1024, RED = 1536;
    constexpr int ABO = 2048, BBO = 5888;
    constexpr int NC = 16;                        // 16 K32-chunks

    float* sv  = (float*)(smu + SV);
    float* so1 = (float*)(smu + SO1);
    float* so2 = (float*)(smu + SO2);
    if (tid < 512) {
        sv[tid]  = v[tid];
        so1[tid] = off1[b * 512 + tid];
        if (DUAL) so2[tid] = off2[b * 512 + tid];
    }

    // ldmatrix per-lane base offsets (bytes)
    const int lt = lane >> 3, lj = lane & 7;
    const uint32_t a_lane = ((wm * 32 + (lt & 1) * 8 + lj) * 20 + (lt >> 1) * 4) * 4;
    const uint32_t b_lane = ((wn * 64 + (lt >> 1) * 8 + lj) * 20 + (lt & 1) * 4) * 4;

    // chunk c: k = c*32; buffer c%3
    auto issue = [&](int c) {
        if (c < NC) {
            const int buf = c % 3;
            const int kc  = c << 5;               // in halves
            const uint32_t ab = sbase + (ABO + buf * 1280) * 4;
            const uint32_t bb = sbase + (BBO + buf * 10240) * 4;
            if (tid < 256) {                      // A: 256 cp16 (64 rows x 4)
                int m = tid >> 2, q = tid & 3;
                cp16(ab + (m * 20 + q * 4) * 4, A + (size_t)(m0 + m) * 512 + kc + q * 8);
            }
#pragma unroll
            for (int j = 0; j < 4; j++) {         // B: 2048 cp16 (512 rows x 4)
                int o = tid + 512 * j, n = o >> 2, q = o & 3;
                cp16(bb + (n * 20 + q * 4) * 4, W + (size_t)n * 512 + kc + q * 8);
            }
        }
        asm volatile("cp.async.commit_group;");
    };

    float acc[2][8][4];
#pragma unroll
    for (int mb = 0; mb < 2; mb++)
#pragma unroll
        for (int nb = 0; nb < 8; nb++)
#pragma unroll
            for (int r = 0; r < 4; r++) acc[mb][nb][r] = 0.f;

    issue(0); issue(1);

    for (int c = 0; c < NC; c++) {
        asm volatile("cp.async.wait_group 1;");
        __syncthreads();          // chunk c landed; everyone done computing c-1
        issue(c + 2);

        const int buf = c % 3;
        const uint32_t abuf = sbase + (ABO + buf * 1280) * 4 + a_lane;
        const uint32_t bbuf = sbase + (BBO + buf * 10240) * 4 + b_lane;
#pragma unroll
        for (int ks = 0; ks < 2; ks++) {          // two K=16 steps
            uint32_t afr[2][4], bfr[8][2];
#pragma unroll
            for (int mb = 0; mb < 2; mb++)
                ldsm4(afr[mb][0], afr[mb][1], afr[mb][2], afr[mb][3],
                      abuf + (mb * 320 + ks * 8) * 4);
#pragma unroll
            for (int p = 0; p < 4; p++)
                ldsm4(bfr[2*p][0], bfr[2*p][1], bfr[2*p+1][0], bfr[2*p+1][1],
                      bbuf + (p * 320 + ks * 8) * 4);
#pragma unroll
            for (int mb = 0; mb < 2; mb++)
#pragma unroll
                for (int nb = 0; nb < 8; nb++)
                    MMA_F16(acc[mb][nb], afr[mb], bfr[nb]);
        }
    }

    // ---- fused epilogue over this warp's 64 columns ----
    float s[4];
#pragma unroll
    for (int i = 0; i < 4; i++) s[i] = 0.f;
#pragma unroll
    for (int mb = 0; mb < 2; mb++)
#pragma unroll
        for (int nb = 0; nb < 8; nb++) {
            int col = wn * 64 + nb * 8 + lq * 2;
#pragma unroll
            for (int r = 0; r < 4; r++) {
                int cc = col + (r & 1);
                float av = acc[mb][nb][r];
                float t1 = fast_tanh(av + so1[cc]);
                float val;
                if (DUAL) {
                    float t2 = fast_tanh(av + so2[cc]);
                    val = sv[cc] * (5.f * t1 + t2);
                } else {
                    val = sv[cc] * t1;
                }
                s[mb * 2 + (r >> 1)] += val;
            }
        }

    // ---- final reduction: quad shuffle, cross-warp smem ----
#pragma unroll
    for (int i = 0; i < 4; i++) {
        s[i] += __shfl_xor_sync(0xffffffffu, s[i], 1);
        s[i] += __shfl_xor_sync(0xffffffffu, s[i], 2);
    }
    float* red = (float*)(smu + RED);  // [64 rows][8 wn]
    __syncthreads();
    if (lq == 0) {
#pragma unroll
        for (int i = 0; i < 4; i++) {
            int row = wm * 32 + (i >> 1) * 16 + (i & 1) * 8 + lg;
            red[row * 8 + wn] = s[i];
        }
    }
    __syncthreads();
    if (tid < 64) {
        float* rr = red + tid * 8;
        out[m0 + tid] = rr[0] + rr[1] + rr[2] + rr[3] + rr[4] + rr[5] + rr[6] + rr[7];
    }
}

// ---------------- small NT GEMM: warp per output element ----------------
__global__ void small_gemm(const float* __restrict__ A, int lda,
                           const float* __restrict__ W, int ldw,
                           const float* __restrict__ Cinit,
                           float* __restrict__ C, int N)
{
    int m = blockIdx.y;
    int n = blockIdx.x * 8 + (threadIdx.x >> 5);
    int lane = threadIdx.x & 31;
    if (n >= N) return;
    const float* a = A + (size_t)m * lda;
    const float* w = W + (size_t)n * ldw;
    float sum = 0.f;
#pragma unroll
    for (int c = 0; c < 4; c++) {
        int k = c * 128 + lane * 4;
        float4 av = *(const float4*)(a + k);
        float4 wv = *(const float4*)(w + k);
        sum += av.x*wv.x + av.y*wv.y + av.z*wv.z + av.w*wv.w;
    }
#pragma unroll
    for (int o = 16; o; o >>= 1) sum += __shfl_xor_sync(0xffffffffu, sum, o);
    if (lane == 0) {
        float base = Cinit ? Cinit[(size_t)m * N + n] : 0.f;
        C[(size_t)m * N + n] = base + sum;
    }
}

// ---------------- GRU gates ----------------
__global__ void gru_gate(const float* __restrict__ bih, const float* __restrict__ bhh,
                         const float* __restrict__ hprev, float* __restrict__ hnew)
{
    int b = blockIdx.x, h = threadIdx.x;
    const float* gx = g_gx + b * 1536;
    const float* gh = g_gh + b * 1536;
    float r = 1.f / (1.f + expf(-(gx[h]     + bih[h]     + gh[h]     + bhh[h])));
    float z = 1.f / (1.f + expf(-(gx[512+h] + bih[512+h] + gh[512+h] + bhh[512+h])));
    float n = tanhf(gx[1024+h] + bih[1024+h] + r * (gh[1024+h] + bhh[1024+h]));
    float hp = hprev[b*512 + h];
    hnew[b*512 + h] = (1.f - z) * n + z * hp;
}

// ---------------- softmax over N=512 (in place), one row per block ----------------
__global__ void softmax512(float* __restrict__ data)
{
    int row = blockIdx.x;
    float* p = data + (size_t)row * 512;
    int tid = threadIdx.x; // 256
    float v0 = p[tid], v1 = p[tid + 256];
    __shared__ float sm[8];
    float mx = fmaxf(v0, v1);
#pragma unroll
    for (int o = 16; o; o >>= 1) mx = fmaxf(mx, __shfl_xor_sync(0xffffffffu, mx, o));
    if ((tid & 31) == 0) sm[tid >> 5] = mx;
    __syncthreads();
    float m = sm[0];
#pragma unroll
    for (int i = 1; i < 8; i++) m = fmaxf(m, sm[i]);
    float e0 = expf(v0 - m), e1 = expf(v1 - m);
    __syncthreads();
    float ss = e0 + e1;
#pragma unroll
    for (int o = 16; o; o >>= 1) ss += __shfl_xor_sync(0xffffffffu, ss, o);
    if ((tid & 31) == 0) sm[tid >> 5] = ss;
    __syncthreads();
    float tot = sm[0]+sm[1]+sm[2]+sm[3]+sm[4]+sm[5]+sm[6]+sm[7];
    float inv = 1.f / tot;
    p[tid] = e0 * inv;
    p[tid + 256] = e1 * inv;
}

// ---------------- both contexts in one pass over static_hidden ----------------
__global__ void context_kernel(const float* __restrict__ sh,
                               const float* __restrict__ attn, // [2*B][512]
                               float* __restrict__ ctx, float* __restrict__ ctxt)
{
    int b = blockIdx.x;
    int h = threadIdx.x; // 512
    __shared__ float ae[512], at[512];
    ae[h] = attn[b*512 + h];
    at[h] = attn[65536 + b*512 + h];
    __syncthreads();
    const float* sp = sh + (size_t)b * 512 * 512 + h;
    float ce = 0.f, ctv = 0.f;
#pragma unroll 4
    for (int n = 0; n < 512; n++) {
        float sv2 = sp[(size_t)n * 512];
        ce  = fmaf(ae[n], sv2, ce);
        ctv = fmaf(at[n], sv2, ctv);
    }
    ctx[b*512 + h] = ce;
    ctxt[b*512 + h] = ctv;
}

// ---------------- host ----------------
static void* sym_addr(const void* s)
{
    void* p = nullptr;
    cudaGetSymbolAddress(&p, s);
    return p;
}

extern "C" void kernel_launch(void* const* d_in, const int* in_sizes, int n_in,
                              void* d_out, int out_size)
{
    const float* static_h  = (const float*)d_in[0];
    const float* state_emb = (const float*)d_in[1];
    const float* dec_h     = (const float*)d_in[2];
    const float* tgt_h     = (const float*)d_in[3];
    const float* last_hh   = (const float*)d_in[4];
    const float* ptr_v     = (const float*)d_in[5];
    const float* ptr_W     = (const float*)d_in[6];
    const float* enc_v     = (const float*)d_in[7];
    const float* enc_W     = (const float*)d_in[8];
    const float* tgt_v     = (const float*)d_in[9];
    const float* tgt_W     = (const float*)d_in[10];
    const float* w_ih      = (const float*)d_in[11];
    const float* w_hh      = (const float*)d_in[12];
    const float* b_ih      = (const float*)d_in[13];
    const float* b_hh      = (const float*)d_in[14];

    float* out  = (float*)d_out;        // probs: [0, 65536)
    float* hnew = out + 65536;          // new_last_hh: [65536, 131072)

    float* p_gx      = (float*)sym_addr(g_gx);
    float* p_gh      = (float*)sym_addr(g_gh);
    float* p_off_enc = (float*)sym_addr(g_off_enc);
    float* p_off_tgt = (float*)sym_addr(g_off_tgt);
    float* p_off_st  = (float*)sym_addr(g_off_state);
    float* p_offP    = (float*)sym_addr(g_offP);
    float* p_offPt   = (float*)sym_addr(g_offPt);
    float* p_scores  = (float*)sym_addr(g_scores);
    float* p_ctx     = (float*)sym_addr(g_ctx);
    float* p_ctxt    = (float*)sym_addr(g_ctxt);
    __half* p_Ah     = (__half*)sym_addr(g_Ah);
    __half* p_Wenc   = (__half*)sym_addr(g_Wenc);
    __half* p_Wtgt   = (__half*)sym_addr(g_Wtgt);
    __half* p_Wptr   = (__half*)sym_addr(g_Wptr);

    constexpr int SMEM_BYTES = 36608 * 4;   // 143 KB
    cudaFuncSetAttribute(tc_mma<false>, cudaFuncAttributeMaxDynamicSharedMemorySize, SMEM_BYTES);
    cudaFuncSetAttribute(tc_mma<true>,  cudaFuncAttributeMaxDynamicSharedMemorySize, SMEM_BYTES);

    dim3 g192(192, 128), g64(64, 128);

    // ---- launches 1-5 (so launch 6 = tc_mma<false> tgt, captured by ncu -s 5 -c 1) ----
    f2h_a<<<16384, 256>>>(static_h, p_Ah);                                           // 1
    f2h_w<<<512, 64>>>(tgt_W, 1024, p_Wtgt);                                         // 2
    small_gemm<<<g64, 256>>>(tgt_h, 512, tgt_W + 512, 1024, nullptr, p_off_tgt, 512);// 3
    f2h_w<<<512, 64>>>(enc_W, 1024, p_Wenc);                                         // 4
    f2h_w<<<512, 64>>>(ptr_W, 1536, p_Wptr);                                         // 5

    // ---- launch 6: big tgt GEMM (profiled) ----
    tc_mma<false><<<1024, 512, SMEM_BYTES>>>(p_Ah, p_Wtgt, p_off_tgt, nullptr, tgt_v,
                                             p_scores + 65536);                     // 6

    // GRU chain + enc offset
    small_gemm<<<g192, 256>>>(dec_h,   512, w_ih, 512, nullptr, p_gx, 1536);         // 7
    small_gemm<<<g192, 256>>>(last_hh, 512, w_hh, 512, nullptr, p_gh, 1536);         // 8
    gru_gate<<<128, 512>>>(b_ih, b_hh, last_hh, hnew);                               // 9
    small_gemm<<<g64, 256>>>(hnew, 512, enc_W + 512, 1024, nullptr, p_off_enc, 512); // 10

    // big enc GEMM
    tc_mma<false><<<1024, 512, SMEM_BYTES>>>(p_Ah, p_Wenc, p_off_enc, nullptr, enc_v,
                                             p_scores);                              // 11

    small_gemm<<<g64, 256>>>(state_emb, 512, ptr_W + 1024, 1536, nullptr, p_off_st, 512); // 12

    // softmax both attentions, then both contexts in one static pass
    softmax512<<<256, 256>>>(p_scores);                                              // 13
    context_kernel<<<128, 512>>>(static_h, p_scores, p_ctx, p_ctxt);                 // 14

    // pointer offsets (context part + state part)
    small_gemm<<<g64, 256>>>(p_ctx,  512, ptr_W + 512, 1536, p_off_st, p_offP,  512);// 15
    small_gemm<<<g64, 256>>>(p_ctxt, 512, ptr_W + 512, 1536, p_off_st, p_offPt, 512);// 16

    // final fused pointer GEMM: 5*tanh(S+offP) + tanh(S+offPt), dot ptr_v
    tc_mma<true><<<1024, 512, SMEM_BYTES>>>(p_Ah, p_Wptr, p_offP, p_offPt, ptr_v, out); // 17
}